// round 14
// baseline (speedup 1.0000x reference)
#include <cuda_runtime.h>
#include <cuda_fp16.h>
#include <math.h>
#include <stdint.h>

// ---------------- problem constants ----------------
#define N_NODES 10000
#define N_EDGES 160000
#define IN_DIM  256
#define HID_DIM 512
#define OUT_DIM 256

// ---------------- device scratch (no allocs allowed; zero-initialized at load) ----------------
__device__ __half g_bufH[N_NODES * HID_DIM];     // GEMM fp16 output (scaled)
__device__ __half g_hiA[N_NODES * HID_DIM];      // fp16 activation buffer A
__device__ __half g_hiB[N_NODES * HID_DIM];      // fp16 activation buffer B
__device__ __half g_W1t[IN_DIM * HID_DIM];       // W^T fp16
__device__ __half g_W2t[HID_DIM * HID_DIM];
__device__ __half g_W3t[HID_DIM * OUT_DIM];
__device__ float  g_dinv[N_NODES];
__device__ int    g_cnt[N_NODES];                // ==0 at every call: static init + scan re-zeroes
__device__ int    g_rowptr[N_NODES + 1];
__device__ int    g_cursor[N_NODES];
__device__ int    g_colsrc[N_EDGES];

__device__ __forceinline__ uint32_t pack2h(float a, float b) {
    __half2 h = __floats2half2_rn(a, b);
    return *reinterpret_cast<uint32_t*>(&h);
}

// ---------------- W -> W^T fp16 (runs on side stream, overlapped with CSR chain) ----------------
#define WTOT (IN_DIM * HID_DIM + HID_DIM * HID_DIM + HID_DIM * OUT_DIM)   // 524288
__global__ void prep_w_kernel(const float* __restrict__ W1, const float* __restrict__ W2,
                              const float* __restrict__ W3,
                              __half* __restrict__ w1t, __half* __restrict__ w2t,
                              __half* __restrict__ w3t) {
    const int S1 = IN_DIM * HID_DIM;
    const int S2 = S1 + HID_DIM * HID_DIM;
    int i = blockIdx.x * blockDim.x + threadIdx.x;
    if (i >= WTOT) return;
    if (i < S1) {
        int k = i / HID_DIM, n = i % HID_DIM;
        w1t[(size_t)n * IN_DIM + k] = __float2half_rn(W1[i]);
    } else if (i < S2) {
        int j = i - S1;
        int k = j / HID_DIM, n = j % HID_DIM;
        w2t[(size_t)n * HID_DIM + k] = __float2half_rn(W2[j]);
    } else {
        int j = i - S2;
        int k = j / OUT_DIM, n = j % OUT_DIM;
        w3t[(size_t)n * HID_DIM + k] = __float2half_rn(W3[j]);
    }
}

// ---------------- edge degree count (cnt==0 on entry, invariant restored by scan) ----------------
__global__ void count_edges_kernel(const int* __restrict__ ei, int* cnt, int E) {
    int e = (blockIdx.x * blockDim.x + threadIdx.x) * 2;
    if (e < E) {
        int d = ei[E + e];
        if (d >= 0 && d < N_NODES) atomicAdd(&cnt[d], 1);
    }
    if (e + 1 < E) {
        int d = ei[E + e + 1];
        if (d >= 0 && d < N_NODES) atomicAdd(&cnt[d], 1);
    }
}

// ---------------- scan: prefix over cnt -> rowptr/cursor, dinv; re-zero cnt ----------------
__global__ void scan_kernel(int* __restrict__ cnt, int* rowptr, int* cursor,
                            float* dinv, int n) {
    __shared__ int ssum[1024];
    int tid = threadIdx.x;
    const int CH = (n + 1023) / 1024;
    int base = tid * CH;
    int local = 0;
    for (int i = 0; i < CH; i++) {
        int idx = base + i;
        if (idx < n) local += cnt[idx];
    }
    ssum[tid] = local;
    __syncthreads();
    for (int off = 1; off < 1024; off <<= 1) {
        int v = ssum[tid];
        int add = (tid >= off) ? ssum[tid - off] : 0;
        __syncthreads();
        ssum[tid] = v + add;
        __syncthreads();
    }
    int run = (tid > 0) ? ssum[tid - 1] : 0;
    for (int i = 0; i < CH; i++) {
        int idx = base + i;
        if (idx < n) {
            rowptr[idx] = run;
            cursor[idx] = run;
            int c = cnt[idx];
            run += c;
            dinv[idx] = rsqrtf((float)c + 1.0f);
            cnt[idx] = 0;   // restore invariant for the next graph replay
        }
    }
    if (tid == 1023) rowptr[n] = run;
}

__global__ void fill_csr_kernel(const int* __restrict__ ei, int* cursor,
                                int* colsrc, int E) {
    int e = (blockIdx.x * blockDim.x + threadIdx.x) * 2;
    if (e < E) {
        int s = ei[e];
        int d = ei[E + e];
        if (d >= 0 && d < N_NODES) {
            int p = atomicAdd(&cursor[d], 1);
            colsrc[p] = s;
        }
    }
    if (e + 1 < E) {
        int s = ei[e + 1];
        int d = ei[E + e + 1];
        if (d >= 0 && d < N_NODES) {
            int p = atomicAdd(&cursor[d], 1);
            colsrc[p] = s;
        }
    }
}

// ---------------- layer-1 pre-aggregation on fp32 x (256-wide gather) ----------------
__global__ void agg_x_kernel(const float* __restrict__ X,
                             const float* __restrict__ dinv,
                             const int* __restrict__ rowptr,
                             const int* __restrict__ colsrc,
                             uint2* __restrict__ outH)
{
    const int F4 = IN_DIM / 4;   // 64
    int i = blockIdx.x;
    int t = threadIdx.x;
    const float4* X4 = (const float4*)X;

    float di = dinv[i];
    float4 xv = __ldg(&X4[(size_t)i * F4 + t]);
    float4 acc;
    acc.x = xv.x * di; acc.y = xv.y * di; acc.z = xv.z * di; acc.w = xv.w * di;

    int e   = rowptr[i];
    int end = rowptr[i + 1];
    for (; e + 4 <= end; e += 4) {
        int s0 = __ldg(&colsrc[e + 0]);
        int s1 = __ldg(&colsrc[e + 1]);
        int s2 = __ldg(&colsrc[e + 2]);
        int s3 = __ldg(&colsrc[e + 3]);
        float w0 = __ldg(&dinv[s0]);
        float w1 = __ldg(&dinv[s1]);
        float w2 = __ldg(&dinv[s2]);
        float w3 = __ldg(&dinv[s3]);
        float4 v0 = __ldg(&X4[(size_t)s0 * F4 + t]);
        float4 v1 = __ldg(&X4[(size_t)s1 * F4 + t]);
        float4 v2 = __ldg(&X4[(size_t)s2 * F4 + t]);
        float4 v3 = __ldg(&X4[(size_t)s3 * F4 + t]);
        acc.x = fmaf(v0.x, w0, fmaf(v1.x, w1, fmaf(v2.x, w2, fmaf(v3.x, w3, acc.x))));
        acc.y = fmaf(v0.y, w0, fmaf(v1.y, w1, fmaf(v2.y, w2, fmaf(v3.y, w3, acc.y))));
        acc.z = fmaf(v0.z, w0, fmaf(v1.z, w1, fmaf(v2.z, w2, fmaf(v3.z, w3, acc.z))));
        acc.w = fmaf(v0.w, w0, fmaf(v1.w, w1, fmaf(v2.w, w2, fmaf(v3.w, w3, acc.w))));
    }
    for (; e < end; ++e) {
        int s = __ldg(&colsrc[e]);
        float w = __ldg(&dinv[s]);
        float4 v = __ldg(&X4[(size_t)s * F4 + t]);
        acc.x = fmaf(v.x, w, acc.x); acc.y = fmaf(v.y, w, acc.y);
        acc.z = fmaf(v.z, w, acc.z); acc.w = fmaf(v.w, w, acc.w);
    }

    outH[(size_t)i * F4 + t] = make_uint2(pack2h(acc.x * di, acc.y * di),
                                          pack2h(acc.z * di, acc.w * di));
}

// ---------------- mma.sync fp16 GEMM, 2-stage double buffer (proven R11 config) ----------------
#define TILE_B 8192
#define STAGE_B (2 * TILE_B)       // 16384
#define GEMM_SMEM (2 * STAGE_B)    // 32768

__device__ __forceinline__ uint32_t swz(uint32_t row, uint32_t c) {
    return ((row >> 1) << 7) | ((((((row & 1u) << 2) | c)) ^ ((row >> 1) & 3u)) << 4);
}
__device__ __forceinline__ void cp16(uint32_t dst, const void* src, bool pred) {
    int sz = pred ? 16 : 0;
    asm volatile("cp.async.cg.shared.global [%0], [%1], 16, %2;"
                 :: "r"(dst), "l"(src), "r"(sz) : "memory");
}
__device__ __forceinline__ void mma_f16(float c[4], const uint32_t a[4], const uint32_t b[2]) {
    asm volatile(
        "mma.sync.aligned.m16n8k16.row.col.f32.f16.f16.f32 "
        "{%0,%1,%2,%3}, {%4,%5,%6,%7}, {%8,%9}, {%0,%1,%2,%3};"
        : "+f"(c[0]), "+f"(c[1]), "+f"(c[2]), "+f"(c[3])
        : "r"(a[0]), "r"(a[1]), "r"(a[2]), "r"(a[3]), "r"(b[0]), "r"(b[1]));
}
__device__ __forceinline__ void ldsm_x4(uint32_t r[4], uint32_t addr) {
    asm volatile("ldmatrix.sync.aligned.m8n8.x4.shared.b16 {%0,%1,%2,%3}, [%4];"
                 : "=r"(r[0]), "=r"(r[1]), "=r"(r[2]), "=r"(r[3]) : "r"(addr));
}
__device__ __forceinline__ void ldsm_x2(uint32_t r[2], uint32_t addr) {
    asm volatile("ldmatrix.sync.aligned.m8n8.x2.shared.b16 {%0,%1}, [%2];"
                 : "=r"(r[0]), "=r"(r[1]) : "r"(addr));
}
__device__ __forceinline__ uint32_t smem_u32p(const void* p) {
    uint32_t a;
    asm("{ .reg .u64 t; cvta.to.shared.u64 t, %1; cvt.u32.u64 %0, t; }" : "=r"(a) : "l"(p));
    return a;
}

template <int EPI_TANH>
__global__ __launch_bounds__(256, 2) void gemm_mma_kernel(
    const uint32_t* __restrict__ A2, const uint32_t* __restrict__ B2,
    const float* __restrict__ dinv, const float* __restrict__ bias,
    uint32_t* __restrict__ Ch,
    int Mm, int Nn, int Kk)
{
    extern __shared__ __align__(16) uint32_t sm[];
    const uint32_t sb = smem_u32p(sm);

    const int tid = threadIdx.x;
    const int wid = tid >> 5;
    const int lid = tid & 31;
    const int g = lid >> 2;
    const int t = lid & 3;
    const int row0 = blockIdx.y * 128;
    const int col0 = blockIdx.x * 128;
    const int m0 = (wid & 1) * 64;
    const int n0 = (wid >> 1) * 32;
    const int Ku = Kk >> 1;

    float acc[4][4][4];
#pragma unroll
    for (int mt = 0; mt < 4; mt++)
#pragma unroll
        for (int nt = 0; nt < 4; nt++)
#pragma unroll
            for (int i = 0; i < 4; i++) acc[mt][nt][i] = 0.0f;

    auto load_tiles = [&](int buf, int kt) {
        const int k0u = kt * 16;
#pragma unroll
        for (int it = 0; it < 4; it++) {
            int c = it * 256 + tid;
            int tile = c >> 9;
            int r = (c >> 2) & 127;
            int ch = c & 3;
            uint32_t dst = sb + (uint32_t)(buf * STAGE_B + tile * TILE_B) + swz((uint32_t)r, (uint32_t)ch);
            const uint32_t* src;
            bool p = true;
            if (tile == 0) {
                int gr = row0 + r;
                p = gr < Mm;
                int gra = p ? gr : 0;
                src = A2 + (size_t)gra * Ku + k0u + ch * 4;
            } else {
                int gn = col0 + r;
                src = B2 + (size_t)gn * Ku + k0u + ch * 4;
            }
            cp16(dst, src, p);
        }
        asm volatile("cp.async.commit_group;" ::: "memory");
    };

    const int nkt = Kk / 32;
    load_tiles(0, 0);

    const uint32_t aR = (uint32_t)(m0 + (lid & 15));
    const uint32_t aC = (uint32_t)(lid >> 4);
    const uint32_t bR = (uint32_t)(n0 + (lid & 7));
    const uint32_t bC = (uint32_t)((lid >> 3) & 1);

    for (int kt = 0; kt < nkt; kt++) {
        int buf = kt & 1;
        if (kt + 1 < nkt) {
            load_tiles(buf ^ 1, kt + 1);
            asm volatile("cp.async.wait_group 1;" ::: "memory");
        } else {
            asm volatile("cp.async.wait_group 0;" ::: "memory");
        }
        __syncthreads();

        const uint32_t base = sb + (uint32_t)(buf * STAGE_B);

#pragma unroll
        for (int ks = 0; ks < 2; ks++) {
            uint32_t ah[4][4];
            uint32_t bq[4][2];
#pragma unroll
            for (int mt = 0; mt < 4; mt++)
                ldsm_x4(ah[mt], base + swz(aR + mt * 16, aC + ks * 2));
#pragma unroll
            for (int nt = 0; nt < 4; nt++)
                ldsm_x2(bq[nt], base + TILE_B + swz(bR + nt * 8, bC + ks * 2));

#pragma unroll
            for (int mt = 0; mt < 4; mt++)
#pragma unroll
                for (int nt = 0; nt < 4; nt++)
                    mma_f16(acc[mt][nt], ah[mt], bq[nt]);
        }
        __syncthreads();
    }

    // ---- epilogue (packed half2 out) ----
#pragma unroll
    for (int mt = 0; mt < 4; mt++) {
        int r0 = row0 + m0 + mt * 16 + g;
        int r1 = r0 + 8;
        if (EPI_TANH) {
#pragma unroll
            for (int nt = 0; nt < 4; nt++) {
                int cn = col0 + n0 + nt * 8 + t * 2;
                float bx = bias[cn], by = bias[cn + 1];
                if (r0 < Mm)
                    Ch[((size_t)r0 * Nn + cn) >> 1] =
                        pack2h(tanhf(acc[mt][nt][0] + bx), tanhf(acc[mt][nt][1] + by));
                if (r1 < Mm)
                    Ch[((size_t)r1 * Nn + cn) >> 1] =
                        pack2h(tanhf(acc[mt][nt][2] + bx), tanhf(acc[mt][nt][3] + by));
            }
        } else {
            float s0 = (r0 < Mm) ? dinv[r0] : 0.0f;
            float s1 = (r1 < Mm) ? dinv[r1] : 0.0f;
#pragma unroll
            for (int nt = 0; nt < 4; nt++) {
                int cn = col0 + n0 + nt * 8 + t * 2;
                if (r0 < Mm)
                    Ch[((size_t)r0 * Nn + cn) >> 1] = pack2h(acc[mt][nt][0] * s0, acc[mt][nt][1] * s0);
                if (r1 < Mm)
                    Ch[((size_t)r1 * Nn + cn) >> 1] = pack2h(acc[mt][nt][2] * s1, acc[mt][nt][3] * s1);
            }
        }
    }
}

// ---------------- aggregation over fp16 G ----------------
template <int APPLY_TANH, int FP16_OUT>
__global__ void agg_kernel_t(const __half* __restrict__ G,
                             const float* __restrict__ bias,
                             const float* __restrict__ dinv,
                             const int* __restrict__ rowptr,
                             const int* __restrict__ colsrc,
                             float* __restrict__ outF,
                             uint2* __restrict__ outH,
                             int F4)
{
    int i = blockIdx.x;
    int t = threadIdx.x;
    const uint2* G4 = (const uint2*)G;

    auto unpack_add = [](float4& a, uint2 v) {
        __half2 p0 = *reinterpret_cast<__half2*>(&v.x);
        __half2 p1 = *reinterpret_cast<__half2*>(&v.y);
        float2 f0 = __half22float2(p0);
        float2 f1 = __half22float2(p1);
        a.x += f0.x; a.y += f0.y; a.z += f1.x; a.w += f1.y;
    };

    float4 acc = make_float4(0.f, 0.f, 0.f, 0.f);
    unpack_add(acc, __ldg(&G4[(size_t)i * F4 + t]));

    int e   = rowptr[i];
    int end = rowptr[i + 1];
    for (; e + 4 <= end; e += 4) {
        int s0 = __ldg(&colsrc[e + 0]);
        int s1 = __ldg(&colsrc[e + 1]);
        int s2 = __ldg(&colsrc[e + 2]);
        int s3 = __ldg(&colsrc[e + 3]);
        uint2 v0 = __ldg(&G4[(size_t)s0 * F4 + t]);
        uint2 v1 = __ldg(&G4[(size_t)s1 * F4 + t]);
        uint2 v2 = __ldg(&G4[(size_t)s2 * F4 + t]);
        uint2 v3 = __ldg(&G4[(size_t)s3 * F4 + t]);
        unpack_add(acc, v0); unpack_add(acc, v1);
        unpack_add(acc, v2); unpack_add(acc, v3);
    }
    for (; e < end; ++e) {
        int s = __ldg(&colsrc[e]);
        unpack_add(acc, __ldg(&G4[(size_t)s * F4 + t]));
    }

    float di = dinv[i];
    float4 bb = ((const float4*)bias)[t];
    float4 r;
    r.x = fmaf(acc.x, di, bb.x);
    r.y = fmaf(acc.y, di, bb.y);
    r.z = fmaf(acc.z, di, bb.z);
    r.w = fmaf(acc.w, di, bb.w);
    if (APPLY_TANH) {
        r.x = tanhf(r.x); r.y = tanhf(r.y);
        r.z = tanhf(r.z); r.w = tanhf(r.w);
    }
    if (FP16_OUT) {
        outH[(size_t)i * F4 + t] = make_uint2(pack2h(r.x, r.y), pack2h(r.z, r.w));
    } else {
        ((float4*)outF)[(size_t)i * F4 + t] = r;
    }
}

// ---------------- launch ----------------
extern "C" void kernel_launch(void* const* d_in, const int* in_sizes, int n_in,
                              void* d_out, int out_size) {
    const float* x  = (const float*)d_in[0];
    const float* W1 = (const float*)d_in[1];
    const float* b1 = (const float*)d_in[2];
    const float* W2 = (const float*)d_in[3];
    const float* b2 = (const float*)d_in[4];
    const float* W3 = (const float*)d_in[5];
    const float* b3 = (const float*)d_in[6];
    const int*   ei = (const int*)d_in[7];    // int32 edge_index [2, E]
    float* out = (float*)d_out;

    const int N = N_NODES;
    const int E = in_sizes[7] / 2;

    float *dinv;
    int *cnt, *rowptr, *cursor, *colsrc;
    __half *bufH, *hiA, *hiB, *w1t, *w2t, *w3t;
    cudaGetSymbolAddress((void**)&bufH,   g_bufH);
    cudaGetSymbolAddress((void**)&dinv,   g_dinv);
    cudaGetSymbolAddress((void**)&cnt,    g_cnt);
    cudaGetSymbolAddress((void**)&rowptr, g_rowptr);
    cudaGetSymbolAddress((void**)&cursor, g_cursor);
    cudaGetSymbolAddress((void**)&colsrc, g_colsrc);
    cudaGetSymbolAddress((void**)&hiA,    g_hiA);
    cudaGetSymbolAddress((void**)&hiB,    g_hiB);
    cudaGetSymbolAddress((void**)&w1t,    g_W1t);
    cudaGetSymbolAddress((void**)&w2t,    g_W2t);
    cudaGetSymbolAddress((void**)&w3t,    g_W3t);

    static cudaStream_t sideStream = nullptr;
    static cudaEvent_t evFork = nullptr, evJoin = nullptr;
    if (sideStream == nullptr) {
        cudaFuncSetAttribute(gemm_mma_kernel<0>, cudaFuncAttributeMaxDynamicSharedMemorySize, GEMM_SMEM);
        cudaFuncSetAttribute(gemm_mma_kernel<1>, cudaFuncAttributeMaxDynamicSharedMemorySize, GEMM_SMEM);
        cudaStreamCreateWithFlags(&sideStream, cudaStreamNonBlocking);
        cudaEventCreateWithFlags(&evFork, cudaEventDisableTiming);
        cudaEventCreateWithFlags(&evJoin, cudaEventDisableTiming);
    }

    // --- fork: W conversion on side stream, CSR chain + agg_x on main stream ---
    cudaEventRecord(evFork, 0);
    cudaStreamWaitEvent(sideStream, evFork, 0);
    prep_w_kernel<<<(WTOT + 255) / 256, 256, 0, sideStream>>>(W1, W2, W3, w1t, w2t, w3t);
    cudaEventRecord(evJoin, sideStream);

    count_edges_kernel<<<(E / 2 + 255) / 256, 256>>>(ei, cnt, E);
    scan_kernel<<<1, 1024>>>(cnt, rowptr, cursor, dinv, N);
    fill_csr_kernel<<<(E / 2 + 255) / 256, 256>>>(ei, cursor, colsrc, E);
    agg_x_kernel<<<N, IN_DIM / 4>>>(x, dinv, rowptr, colsrc, (uint2*)hiA);

    // --- join before first GEMM (needs W1t) ---
    cudaStreamWaitEvent(0, evJoin, 0);

    const int MT = (N + 127) / 128;

    // --- layer 1: GEMM with tanh epilogue ---
    {
        dim3 grid(HID_DIM / 128, MT);
        gemm_mma_kernel<1><<<grid, 256, GEMM_SMEM>>>((uint32_t*)hiA, (uint32_t*)w1t,
                                                     nullptr, b1, (uint32_t*)hiB,
                                                     N, HID_DIM, IN_DIM);
    }
    // --- layer 2: GEMM (dinv epi, fp16 out) -> agg(tanh, fp16 out) ---
    {
        dim3 grid(HID_DIM / 128, MT);
        gemm_mma_kernel<0><<<grid, 256, GEMM_SMEM>>>((uint32_t*)hiB, (uint32_t*)w2t,
                                                     dinv, nullptr, (uint32_t*)bufH,
                                                     N, HID_DIM, HID_DIM);
        agg_kernel_t<1, 1><<<N, HID_DIM / 4>>>(bufH, b2, dinv, rowptr, colsrc,
                                               nullptr, (uint2*)hiA, HID_DIM / 4);
    }
    // --- layer 3: GEMM (dinv epi, fp16 out) -> agg(bias, fp32 out) ---
    {
        dim3 grid(OUT_DIM / 128, MT);
        gemm_mma_kernel<0><<<grid, 256, GEMM_SMEM>>>((uint32_t*)hiA, (uint32_t*)w3t,
                                                     dinv, nullptr, (uint32_t*)bufH,
                                                     N, OUT_DIM, HID_DIM);
        agg_kernel_t<0, 0><<<N, OUT_DIM / 4>>>(bufH, b3, dinv, rowptr, colsrc,
                                               out, nullptr, OUT_DIM / 4);
    }
}

// round 15
// speedup vs baseline: 1.0129x; 1.0129x over previous
#include <cuda_runtime.h>
#include <cuda_fp16.h>
#include <math.h>
#include <stdint.h>

// ---------------- problem constants ----------------
#define N_NODES 10000
#define N_EDGES 160000
#define IN_DIM  256
#define HID_DIM 512
#define OUT_DIM 256

// ---------------- device scratch (no allocs allowed; zero-initialized at load) ----------------
__device__ __half g_bufH[N_NODES * HID_DIM];     // GEMM fp16 output (scaled)
__device__ __half g_hiA[N_NODES * HID_DIM];      // fp16 activation buffer A
__device__ __half g_hiB[N_NODES * HID_DIM];      // fp16 activation buffer B
__device__ __half g_W1t[IN_DIM * HID_DIM];       // W^T fp16
__device__ __half g_W2t[HID_DIM * HID_DIM];
__device__ __half g_W3t[HID_DIM * OUT_DIM];
__device__ float  g_dinv[N_NODES];
__device__ int    g_cnt[N_NODES];                // ==0 at every call: static init + scan re-zeroes
__device__ int    g_rowptr[N_NODES + 1];
__device__ int    g_cursor[N_NODES];
__device__ int    g_colsrc[N_EDGES];

__device__ __forceinline__ uint32_t pack2h(float a, float b) {
    __half2 h = __floats2half2_rn(a, b);
    return *reinterpret_cast<uint32_t*>(&h);
}

// ---------------- fused prep: W -> W^T fp16 + edge degree count ----------------
// cnt[] is 0 on entry (static zero-init on first call; scan_kernel re-zeroes after consuming).
#define WTOT (IN_DIM * HID_DIM + HID_DIM * HID_DIM + HID_DIM * OUT_DIM)   // 524288
__global__ void fused_prep_kernel(const float* __restrict__ W1, const float* __restrict__ W2,
                                  const float* __restrict__ W3,
                                  __half* __restrict__ w1t, __half* __restrict__ w2t,
                                  __half* __restrict__ w3t,
                                  const int* __restrict__ ei, int* __restrict__ cnt, int E) {
    const int S1 = IN_DIM * HID_DIM;
    const int S2 = S1 + HID_DIM * HID_DIM;
    int i = blockIdx.x * blockDim.x + threadIdx.x;
    if (i < WTOT) {
        if (i < S1) {
            int k = i / HID_DIM, n = i % HID_DIM;
            w1t[(size_t)n * IN_DIM + k] = __float2half_rn(W1[i]);
        } else if (i < S2) {
            int j = i - S1;
            int k = j / HID_DIM, n = j % HID_DIM;
            w2t[(size_t)n * HID_DIM + k] = __float2half_rn(W2[j]);
        } else {
            int j = i - S2;
            int k = j / OUT_DIM, n = j % OUT_DIM;
            w3t[(size_t)n * HID_DIM + k] = __float2half_rn(W3[j]);
        }
    } else if (i < WTOT + E) {
        int e = i - WTOT;
        int d = ei[E + e];
        if (d >= 0 && d < N_NODES) atomicAdd(&cnt[d], 1);
    }
}

// ---------------- scan: prefix over cnt -> rowptr/cursor, dinv; re-zero cnt ----------------
__global__ void scan_kernel(int* __restrict__ cnt, int* rowptr, int* cursor,
                            float* dinv, int n) {
    __shared__ int ssum[1024];
    int tid = threadIdx.x;
    const int CH = (n + 1023) / 1024;
    int base = tid * CH;
    int local = 0;
    for (int i = 0; i < CH; i++) {
        int idx = base + i;
        if (idx < n) local += cnt[idx];
    }
    ssum[tid] = local;
    __syncthreads();
    for (int off = 1; off < 1024; off <<= 1) {
        int v = ssum[tid];
        int add = (tid >= off) ? ssum[tid - off] : 0;
        __syncthreads();
        ssum[tid] = v + add;
        __syncthreads();
    }
    int run = (tid > 0) ? ssum[tid - 1] : 0;
    for (int i = 0; i < CH; i++) {
        int idx = base + i;
        if (idx < n) {
            rowptr[idx] = run;
            cursor[idx] = run;
            int c = cnt[idx];
            run += c;
            dinv[idx] = rsqrtf((float)c + 1.0f);
            cnt[idx] = 0;   // restore invariant for the next call/replay
        }
    }
    if (tid == 1023) rowptr[n] = run;
}

__global__ void fill_csr_kernel(const int* __restrict__ ei, int* cursor,
                                int* colsrc, int E) {
    int e = (blockIdx.x * blockDim.x + threadIdx.x) * 2;
    if (e < E) {
        int s = ei[e];
        int d = ei[E + e];
        if (d >= 0 && d < N_NODES) {
            int p = atomicAdd(&cursor[d], 1);
            colsrc[p] = s;
        }
    }
    if (e + 1 < E) {
        int s = ei[e + 1];
        int d = ei[E + e + 1];
        if (d >= 0 && d < N_NODES) {
            int p = atomicAdd(&cursor[d], 1);
            colsrc[p] = s;
        }
    }
}

// ---------------- layer-1 pre-aggregation on fp32 x (256-wide gather) ----------------
__global__ void agg_x_kernel(const float* __restrict__ X,
                             const float* __restrict__ dinv,
                             const int* __restrict__ rowptr,
                             const int* __restrict__ colsrc,
                             uint2* __restrict__ outH)
{
    const int F4 = IN_DIM / 4;   // 64
    int i = blockIdx.x;
    int t = threadIdx.x;
    const float4* X4 = (const float4*)X;

    float di = dinv[i];
    float4 xv = __ldg(&X4[(size_t)i * F4 + t]);
    float4 acc;
    acc.x = xv.x * di; acc.y = xv.y * di; acc.z = xv.z * di; acc.w = xv.w * di;

    int e   = rowptr[i];
    int end = rowptr[i + 1];
    for (; e + 2 <= end; e += 2) {
        int s0 = __ldg(&colsrc[e + 0]);
        int s1 = __ldg(&colsrc[e + 1]);
        float w0 = __ldg(&dinv[s0]);
        float w1 = __ldg(&dinv[s1]);
        float4 v0 = __ldg(&X4[(size_t)s0 * F4 + t]);
        float4 v1 = __ldg(&X4[(size_t)s1 * F4 + t]);
        acc.x += v0.x * w0 + v1.x * w1;
        acc.y += v0.y * w0 + v1.y * w1;
        acc.z += v0.z * w0 + v1.z * w1;
        acc.w += v0.w * w0 + v1.w * w1;
    }
    for (; e < end; ++e) {
        int s = __ldg(&colsrc[e]);
        float w = __ldg(&dinv[s]);
        float4 v = __ldg(&X4[(size_t)s * F4 + t]);
        acc.x += v.x * w; acc.y += v.y * w; acc.z += v.z * w; acc.w += v.w * w;
    }

    outH[(size_t)i * F4 + t] = make_uint2(pack2h(acc.x * di, acc.y * di),
                                          pack2h(acc.z * di, acc.w * di));
}

// ---------------- mma.sync fp16 GEMM, 2-stage double buffer, 2 CTAs/SM ----------------
#define TILE_B 8192
#define STAGE_B (2 * TILE_B)       // 16384
#define GEMM_SMEM (2 * STAGE_B)    // 32768

__device__ __forceinline__ uint32_t swz(uint32_t row, uint32_t c) {
    return ((row >> 1) << 7) | ((((((row & 1u) << 2) | c)) ^ ((row >> 1) & 3u)) << 4);
}
__device__ __forceinline__ void cp16(uint32_t dst, const void* src, bool pred) {
    int sz = pred ? 16 : 0;
    asm volatile("cp.async.cg.shared.global [%0], [%1], 16, %2;"
                 :: "r"(dst), "l"(src), "r"(sz) : "memory");
}
__device__ __forceinline__ void mma_f16(float c[4], const uint32_t a[4], const uint32_t b[2]) {
    asm volatile(
        "mma.sync.aligned.m16n8k16.row.col.f32.f16.f16.f32 "
        "{%0,%1,%2,%3}, {%4,%5,%6,%7}, {%8,%9}, {%0,%1,%2,%3};"
        : "+f"(c[0]), "+f"(c[1]), "+f"(c[2]), "+f"(c[3])
        : "r"(a[0]), "r"(a[1]), "r"(a[2]), "r"(a[3]), "r"(b[0]), "r"(b[1]));
}
__device__ __forceinline__ void ldsm_x4(uint32_t r[4], uint32_t addr) {
    asm volatile("ldmatrix.sync.aligned.m8n8.x4.shared.b16 {%0,%1,%2,%3}, [%4];"
                 : "=r"(r[0]), "=r"(r[1]), "=r"(r[2]), "=r"(r[3]) : "r"(addr));
}
__device__ __forceinline__ void ldsm_x2(uint32_t r[2], uint32_t addr) {
    asm volatile("ldmatrix.sync.aligned.m8n8.x2.shared.b16 {%0,%1}, [%2];"
                 : "=r"(r[0]), "=r"(r[1]) : "r"(addr));
}
__device__ __forceinline__ uint32_t smem_u32p(const void* p) {
    uint32_t a;
    asm("{ .reg .u64 t; cvta.to.shared.u64 t, %1; cvt.u32.u64 %0, t; }" : "=r"(a) : "l"(p));
    return a;
}

template <int EPI_TANH>
__global__ __launch_bounds__(256, 2) void gemm_mma_kernel(
    const uint32_t* __restrict__ A2, const uint32_t* __restrict__ B2,
    const float* __restrict__ dinv, const float* __restrict__ bias,
    uint32_t* __restrict__ Ch,
    int Mm, int Nn, int Kk)
{
    extern __shared__ __align__(16) uint32_t sm[];
    const uint32_t sb = smem_u32p(sm);

    const int tid = threadIdx.x;
    const int wid = tid >> 5;
    const int lid = tid & 31;
    const int g = lid >> 2;
    const int t = lid & 3;
    const int row0 = blockIdx.y * 128;
    const int col0 = blockIdx.x * 128;
    const int m0 = (wid & 1) * 64;
    const int n0 = (wid >> 1) * 32;
    const int Ku = Kk >> 1;

    float acc[4][4][4];
#pragma unroll
    for (int mt = 0; mt < 4; mt++)
#pragma unroll
        for (int nt = 0; nt < 4; nt++)
#pragma unroll
            for (int i = 0; i < 4; i++) acc[mt][nt][i] = 0.0f;

    auto load_tiles = [&](int buf, int kt) {
        const int k0u = kt * 16;
#pragma unroll
        for (int it = 0; it < 4; it++) {
            int c = it * 256 + tid;
            int tile = c >> 9;
            int r = (c >> 2) & 127;
            int ch = c & 3;
            uint32_t dst = sb + (uint32_t)(buf * STAGE_B + tile * TILE_B) + swz((uint32_t)r, (uint32_t)ch);
            const uint32_t* src;
            bool p = true;
            if (tile == 0) {
                int gr = row0 + r;
                p = gr < Mm;
                int gra = p ? gr : 0;
                src = A2 + (size_t)gra * Ku + k0u + ch * 4;
            } else {
                int gn = col0 + r;
                src = B2 + (size_t)gn * Ku + k0u + ch * 4;
            }
            cp16(dst, src, p);
        }
        asm volatile("cp.async.commit_group;" ::: "memory");
    };

    const int nkt = Kk / 32;
    load_tiles(0, 0);

    const uint32_t aR = (uint32_t)(m0 + (lid & 15));
    const uint32_t aC = (uint32_t)(lid >> 4);
    const uint32_t bR = (uint32_t)(n0 + (lid & 7));
    const uint32_t bC = (uint32_t)((lid >> 3) & 1);

    for (int kt = 0; kt < nkt; kt++) {
        int buf = kt & 1;
        if (kt + 1 < nkt) {
            load_tiles(buf ^ 1, kt + 1);
            asm volatile("cp.async.wait_group 1;" ::: "memory");
        } else {
            asm volatile("cp.async.wait_group 0;" ::: "memory");
        }
        __syncthreads();

        const uint32_t base = sb + (uint32_t)(buf * STAGE_B);

#pragma unroll
        for (int ks = 0; ks < 2; ks++) {
            uint32_t ah[4][4];
            uint32_t bq[4][2];
#pragma unroll
            for (int mt = 0; mt < 4; mt++)
                ldsm_x4(ah[mt], base + swz(aR + mt * 16, aC + ks * 2));
#pragma unroll
            for (int nt = 0; nt < 4; nt++)
                ldsm_x2(bq[nt], base + TILE_B + swz(bR + nt * 8, bC + ks * 2));

#pragma unroll
            for (int mt = 0; mt < 4; mt++)
#pragma unroll
                for (int nt = 0; nt < 4; nt++)
                    mma_f16(acc[mt][nt], ah[mt], bq[nt]);
        }
        __syncthreads();
    }

    // ---- epilogue (packed half2 out) ----
#pragma unroll
    for (int mt = 0; mt < 4; mt++) {
        int r0 = row0 + m0 + mt * 16 + g;
        int r1 = r0 + 8;
        if (EPI_TANH) {
#pragma unroll
            for (int nt = 0; nt < 4; nt++) {
                int cn = col0 + n0 + nt * 8 + t * 2;
                float bx = bias[cn], by = bias[cn + 1];
                if (r0 < Mm)
                    Ch[((size_t)r0 * Nn + cn) >> 1] =
                        pack2h(tanhf(acc[mt][nt][0] + bx), tanhf(acc[mt][nt][1] + by));
                if (r1 < Mm)
                    Ch[((size_t)r1 * Nn + cn) >> 1] =
                        pack2h(tanhf(acc[mt][nt][2] + bx), tanhf(acc[mt][nt][3] + by));
            }
        } else {
            float s0 = (r0 < Mm) ? dinv[r0] : 0.0f;
            float s1 = (r1 < Mm) ? dinv[r1] : 0.0f;
#pragma unroll
            for (int nt = 0; nt < 4; nt++) {
                int cn = col0 + n0 + nt * 8 + t * 2;
                if (r0 < Mm)
                    Ch[((size_t)r0 * Nn + cn) >> 1] = pack2h(acc[mt][nt][0] * s0, acc[mt][nt][1] * s0);
                if (r1 < Mm)
                    Ch[((size_t)r1 * Nn + cn) >> 1] = pack2h(acc[mt][nt][2] * s1, acc[mt][nt][3] * s1);
            }
        }
    }
}

// ---------------- aggregation over fp16 G ----------------
template <int APPLY_TANH, int FP16_OUT>
__global__ void agg_kernel_t(const __half* __restrict__ G,
                             const float* __restrict__ bias,
                             const float* __restrict__ dinv,
                             const int* __restrict__ rowptr,
                             const int* __restrict__ colsrc,
                             float* __restrict__ outF,
                             uint2* __restrict__ outH,
                             int F4)
{
    int i = blockIdx.x;
    int t = threadIdx.x;
    const uint2* G4 = (const uint2*)G;

    auto unpack_add = [](float4& a, uint2 v) {
        __half2 p0 = *reinterpret_cast<__half2*>(&v.x);
        __half2 p1 = *reinterpret_cast<__half2*>(&v.y);
        float2 f0 = __half22float2(p0);
        float2 f1 = __half22float2(p1);
        a.x += f0.x; a.y += f0.y; a.z += f1.x; a.w += f1.y;
    };

    float4 acc = make_float4(0.f, 0.f, 0.f, 0.f);
    unpack_add(acc, __ldg(&G4[(size_t)i * F4 + t]));

    int e   = rowptr[i];
    int end = rowptr[i + 1];
    for (; e + 4 <= end; e += 4) {
        int s0 = __ldg(&colsrc[e + 0]);
        int s1 = __ldg(&colsrc[e + 1]);
        int s2 = __ldg(&colsrc[e + 2]);
        int s3 = __ldg(&colsrc[e + 3]);
        uint2 v0 = __ldg(&G4[(size_t)s0 * F4 + t]);
        uint2 v1 = __ldg(&G4[(size_t)s1 * F4 + t]);
        uint2 v2 = __ldg(&G4[(size_t)s2 * F4 + t]);
        uint2 v3 = __ldg(&G4[(size_t)s3 * F4 + t]);
        unpack_add(acc, v0); unpack_add(acc, v1);
        unpack_add(acc, v2); unpack_add(acc, v3);
    }
    for (; e < end; ++e) {
        int s = __ldg(&colsrc[e]);
        unpack_add(acc, __ldg(&G4[(size_t)s * F4 + t]));
    }

    float di = dinv[i];
    float4 bb = ((const float4*)bias)[t];
    float4 r;
    r.x = fmaf(acc.x, di, bb.x);
    r.y = fmaf(acc.y, di, bb.y);
    r.z = fmaf(acc.z, di, bb.z);
    r.w = fmaf(acc.w, di, bb.w);
    if (APPLY_TANH) {
        r.x = tanhf(r.x); r.y = tanhf(r.y);
        r.z = tanhf(r.z); r.w = tanhf(r.w);
    }
    if (FP16_OUT) {
        outH[(size_t)i * F4 + t] = make_uint2(pack2h(r.x, r.y), pack2h(r.z, r.w));
    } else {
        ((float4*)outF)[(size_t)i * F4 + t] = r;
    }
}

// ---------------- launch ----------------
extern "C" void kernel_launch(void* const* d_in, const int* in_sizes, int n_in,
                              void* d_out, int out_size) {
    const float* x  = (const float*)d_in[0];
    const float* W1 = (const float*)d_in[1];
    const float* b1 = (const float*)d_in[2];
    const float* W2 = (const float*)d_in[3];
    const float* b2 = (const float*)d_in[4];
    const float* W3 = (const float*)d_in[5];
    const float* b3 = (const float*)d_in[6];
    const int*   ei = (const int*)d_in[7];    // int32 edge_index [2, E]
    float* out = (float*)d_out;

    const int N = N_NODES;
    const int E = in_sizes[7] / 2;

    float *dinv;
    int *cnt, *rowptr, *cursor, *colsrc;
    __half *bufH, *hiA, *hiB, *w1t, *w2t, *w3t;
    cudaGetSymbolAddress((void**)&bufH,   g_bufH);
    cudaGetSymbolAddress((void**)&dinv,   g_dinv);
    cudaGetSymbolAddress((void**)&cnt,    g_cnt);
    cudaGetSymbolAddress((void**)&rowptr, g_rowptr);
    cudaGetSymbolAddress((void**)&cursor, g_cursor);
    cudaGetSymbolAddress((void**)&colsrc, g_colsrc);
    cudaGetSymbolAddress((void**)&hiA,    g_hiA);
    cudaGetSymbolAddress((void**)&hiB,    g_hiB);
    cudaGetSymbolAddress((void**)&w1t,    g_W1t);
    cudaGetSymbolAddress((void**)&w2t,    g_W2t);
    cudaGetSymbolAddress((void**)&w3t,    g_W3t);

    static bool attr_set = false;
    if (!attr_set) {
        cudaFuncSetAttribute(gemm_mma_kernel<0>, cudaFuncAttributeMaxDynamicSharedMemorySize, GEMM_SMEM);
        cudaFuncSetAttribute(gemm_mma_kernel<1>, cudaFuncAttributeMaxDynamicSharedMemorySize, GEMM_SMEM);
        attr_set = true;
    }

    // --- fused prep: W transpose/convert + edge degree count (cnt==0 invariant) ---
    {
        int total = WTOT + E;
        fused_prep_kernel<<<(total + 255) / 256, 256>>>(W1, W2, W3, w1t, w2t, w3t, ei, cnt, E);
    }
    scan_kernel<<<1, 1024>>>(cnt, rowptr, cursor, dinv, N);
    fill_csr_kernel<<<(E / 2 + 255) / 256, 256>>>(ei, cursor, colsrc, E);

    const int MT = (N + 127) / 128;

    // --- layer 1: aggregate fp32 x (256-wide) -> fp16, then GEMM with tanh epilogue ---
    agg_x_kernel<<<N, IN_DIM / 4>>>(x, dinv, rowptr, colsrc, (uint2*)hiA);
    {
        dim3 grid(HID_DIM / 128, MT);
        gemm_mma_kernel<1><<<grid, 256, GEMM_SMEM>>>((uint32_t*)hiA, (uint32_t*)w1t,
                                                     nullptr, b1, (uint32_t*)hiB,
                                                     N, HID_DIM, IN_DIM);
    }
    // --- layer 2: GEMM (dinv epi, fp16 out) -> agg(tanh, fp16 out) ---
    {
        dim3 grid(HID_DIM / 128, MT);
        gemm_mma_kernel<0><<<grid, 256, GEMM_SMEM>>>((uint32_t*)hiB, (uint32_t*)w2t,
                                                     dinv, nullptr, (uint32_t*)bufH,
                                                     N, HID_DIM, HID_DIM);
        agg_kernel_t<1, 1><<<N, HID_DIM / 4>>>(bufH, b2, dinv, rowptr, colsrc,
                                               nullptr, (uint2*)hiA, HID_DIM / 4);
    }
    // --- layer 3: GEMM (dinv epi, fp16 out) -> agg(bias, fp32 out) ---
    {
        dim3 grid(OUT_DIM / 128, MT);
        gemm_mma_kernel<0><<<grid, 256, GEMM_SMEM>>>((uint32_t*)hiA, (uint32_t*)w3t,
                                                     dinv, nullptr, (uint32_t*)bufH,
                                                     N, OUT_DIM, HID_DIM);
        agg_kernel_t<0, 0><<<N, OUT_DIM / 4>>>(bufH, b3, dinv, rowptr, colsrc,
                                               out, nullptr, OUT_DIM / 4);
    }
}

// round 16
// speedup vs baseline: 1.0755x; 1.0618x over previous
#include <cuda_runtime.h>
#include <cuda_fp16.h>
#include <math.h>
#include <stdint.h>

// ---------------- problem constants ----------------
#define N_NODES 10000
#define N_EDGES 160000
#define IN_DIM  256
#define HID_DIM 512
#define OUT_DIM 256

// ---------------- device scratch (no allocs allowed; zero-initialized at load) ----------------
__device__ __half g_bufH[N_NODES * HID_DIM];     // GEMM fp16 output (scaled)
__device__ __half g_hiA[N_NODES * HID_DIM];      // fp16 activation buffer A
__device__ __half g_hiB[N_NODES * HID_DIM];      // fp16 activation buffer B
__device__ __half g_W1t[IN_DIM * HID_DIM];       // W^T fp16
__device__ __half g_W2t[HID_DIM * HID_DIM];
__device__ __half g_W3t[HID_DIM * OUT_DIM];
__device__ float  g_dinv[N_NODES];
__device__ int    g_cnt[N_NODES];
__device__ int    g_rowptr[N_NODES + 1];
__device__ int    g_cursor[N_NODES];
__device__ int    g_colsrc[N_EDGES];

__device__ __forceinline__ uint32_t pack2h(float a, float b) {
    __half2 h = __floats2half2_rn(a, b);
    return *reinterpret_cast<uint32_t*>(&h);
}

// ---------------- fused one-shot prep: W1/W2/W3 -> W^T fp16, cnt zero ----------------
#define WTOT (IN_DIM * HID_DIM + HID_DIM * HID_DIM + HID_DIM * OUT_DIM)   // 524288
__global__ void fused_prep_kernel(const float* __restrict__ W1, const float* __restrict__ W2,
                                  const float* __restrict__ W3,
                                  __half* __restrict__ w1t, __half* __restrict__ w2t,
                                  __half* __restrict__ w3t,
                                  int* __restrict__ cnt) {
    const int S1 = IN_DIM * HID_DIM;
    const int S2 = S1 + HID_DIM * HID_DIM;
    int i = blockIdx.x * blockDim.x + threadIdx.x;
    if (i < WTOT) {
        if (i < S1) {
            int k = i / HID_DIM, n = i % HID_DIM;
            w1t[(size_t)n * IN_DIM + k] = __float2half_rn(W1[i]);
        } else if (i < S2) {
            int j = i - S1;
            int k = j / HID_DIM, n = j % HID_DIM;
            w2t[(size_t)n * HID_DIM + k] = __float2half_rn(W2[j]);
        } else {
            int j = i - S2;
            int k = j / OUT_DIM, n = j % OUT_DIM;
            w3t[(size_t)n * HID_DIM + k] = __float2half_rn(W3[j]);
        }
    } else if (i < WTOT + N_NODES) {
        cnt[i - WTOT] = 0;
    }
}

// ---------------- preprocessing kernels (2 edges/thread) ----------------
__global__ void count_edges_kernel(const int* __restrict__ ei, int* cnt, int E) {
    int e = (blockIdx.x * blockDim.x + threadIdx.x) * 2;
    if (e < E) {
        int d = ei[E + e];
        if (d >= 0 && d < N_NODES) atomicAdd(&cnt[d], 1);
    }
    if (e + 1 < E) {
        int d = ei[E + e + 1];
        if (d >= 0 && d < N_NODES) atomicAdd(&cnt[d], 1);
    }
}

__global__ void scan_kernel(const int* __restrict__ cnt, int* rowptr, int* cursor,
                            float* dinv, int n) {
    __shared__ int ssum[1024];
    int tid = threadIdx.x;
    const int CH = (n + 1023) / 1024;
    int base = tid * CH;
    int local = 0;
    for (int i = 0; i < CH; i++) {
        int idx = base + i;
        if (idx < n) local += cnt[idx];
    }
    ssum[tid] = local;
    __syncthreads();
    for (int off = 1; off < 1024; off <<= 1) {
        int v = ssum[tid];
        int add = (tid >= off) ? ssum[tid - off] : 0;
        __syncthreads();
        ssum[tid] = v + add;
        __syncthreads();
    }
    int run = (tid > 0) ? ssum[tid - 1] : 0;
    for (int i = 0; i < CH; i++) {
        int idx = base + i;
        if (idx < n) {
            rowptr[idx] = run;
            cursor[idx] = run;
            int c = cnt[idx];
            run += c;
            dinv[idx] = rsqrtf((float)c + 1.0f);
        }
    }
    if (tid == 1023) rowptr[n] = run;
}

__global__ void fill_csr_kernel(const int* __restrict__ ei, int* cursor,
                                int* colsrc, int E) {
    int e = (blockIdx.x * blockDim.x + threadIdx.x) * 2;
    if (e < E) {
        int s = ei[e];
        int d = ei[E + e];
        if (d >= 0 && d < N_NODES) {
            int p = atomicAdd(&cursor[d], 1);
            colsrc[p] = s;
        }
    }
    if (e + 1 < E) {
        int s = ei[e + 1];
        int d = ei[E + e + 1];
        if (d >= 0 && d < N_NODES) {
            int p = atomicAdd(&cursor[d], 1);
            colsrc[p] = s;
        }
    }
}

// ---------------- layer-1 pre-aggregation on fp32 x (256-wide gather) -> fp16 ----------------
__global__ void agg_x_kernel(const float* __restrict__ X,
                             const float* __restrict__ dinv,
                             const int* __restrict__ rowptr,
                             const int* __restrict__ colsrc,
                             uint2* __restrict__ outH)
{
    const int F4 = IN_DIM / 4;   // 64
    int i = blockIdx.x;
    int t = threadIdx.x;
    const float4* X4 = (const float4*)X;

    float di = dinv[i];
    float4 xv = __ldg(&X4[(size_t)i * F4 + t]);
    float4 acc;
    acc.x = xv.x * di; acc.y = xv.y * di; acc.z = xv.z * di; acc.w = xv.w * di;

    int e   = rowptr[i];
    int end = rowptr[i + 1];
    for (; e + 2 <= end; e += 2) {
        int s0 = __ldg(&colsrc[e + 0]);
        int s1 = __ldg(&colsrc[e + 1]);
        float w0 = __ldg(&dinv[s0]);
        float w1 = __ldg(&dinv[s1]);
        float4 v0 = __ldg(&X4[(size_t)s0 * F4 + t]);
        float4 v1 = __ldg(&X4[(size_t)s1 * F4 + t]);
        acc.x += v0.x * w0 + v1.x * w1;
        acc.y += v0.y * w0 + v1.y * w1;
        acc.z += v0.z * w0 + v1.z * w1;
        acc.w += v0.w * w0 + v1.w * w1;
    }
    for (; e < end; ++e) {
        int s = __ldg(&colsrc[e]);
        float w = __ldg(&dinv[s]);
        float4 v = __ldg(&X4[(size_t)s * F4 + t]);
        acc.x += v.x * w; acc.y += v.y * w; acc.z += v.z * w; acc.w += v.w * w;
    }

    outH[(size_t)i * F4 + t] = make_uint2(pack2h(acc.x * di, acc.y * di),
                                          pack2h(acc.z * di, acc.w * di));
}

// ---------------- mma.sync fp16 GEMM (single operand pass), 2 CTAs/SM ----------------
#define TILE_B 8192
#define STAGE_B (2 * TILE_B)       // 16384
#define GEMM_SMEM (2 * STAGE_B)    // 32768

__device__ __forceinline__ uint32_t swz(uint32_t row, uint32_t c) {
    return ((row >> 1) << 7) | ((((((row & 1u) << 2) | c)) ^ ((row >> 1) & 3u)) << 4);
}
__device__ __forceinline__ void cp16(uint32_t dst, const void* src, bool pred) {
    int sz = pred ? 16 : 0;
    asm volatile("cp.async.cg.shared.global [%0], [%1], 16, %2;"
                 :: "r"(dst), "l"(src), "r"(sz) : "memory");
}
__device__ __forceinline__ void mma_f16(float c[4], const uint32_t a[4], const uint32_t b[2]) {
    asm volatile(
        "mma.sync.aligned.m16n8k16.row.col.f32.f16.f16.f32 "
        "{%0,%1,%2,%3}, {%4,%5,%6,%7}, {%8,%9}, {%0,%1,%2,%3};"
        : "+f"(c[0]), "+f"(c[1]), "+f"(c[2]), "+f"(c[3])
        : "r"(a[0]), "r"(a[1]), "r"(a[2]), "r"(a[3]), "r"(b[0]), "r"(b[1]));
}
__device__ __forceinline__ void ldsm_x4(uint32_t r[4], uint32_t addr) {
    asm volatile("ldmatrix.sync.aligned.m8n8.x4.shared.b16 {%0,%1,%2,%3}, [%4];"
                 : "=r"(r[0]), "=r"(r[1]), "=r"(r[2]), "=r"(r[3]) : "r"(addr));
}
__device__ __forceinline__ void ldsm_x2(uint32_t r[2], uint32_t addr) {
    asm volatile("ldmatrix.sync.aligned.m8n8.x2.shared.b16 {%0,%1}, [%2];"
                 : "=r"(r[0]), "=r"(r[1]) : "r"(addr));
}
__device__ __forceinline__ uint32_t smem_u32p(const void* p) {
    uint32_t a;
    asm("{ .reg .u64 t; cvta.to.shared.u64 t, %1; cvt.u32.u64 %0, t; }" : "=r"(a) : "l"(p));
    return a;
}

template <int EPI_TANH>
__global__ __launch_bounds__(256, 2) void gemm_mma_kernel(
    const uint32_t* __restrict__ A2, const uint32_t* __restrict__ B2,
    const float* __restrict__ dinv, const float* __restrict__ bias,
    uint32_t* __restrict__ Ch,
    int Mm, int Nn, int Kk)
{
    extern __shared__ __align__(16) uint32_t sm[];
    const uint32_t sb = smem_u32p(sm);

    const int tid = threadIdx.x;
    const int wid = tid >> 5;
    const int lid = tid & 31;
    const int g = lid >> 2;
    const int t = lid & 3;
    const int row0 = blockIdx.y * 128;
    const int col0 = blockIdx.x * 128;
    const int m0 = (wid & 1) * 64;
    const int n0 = (wid >> 1) * 32;
    const int Ku = Kk >> 1;

    float acc[4][4][4];
#pragma unroll
    for (int mt = 0; mt < 4; mt++)
#pragma unroll
        for (int nt = 0; nt < 4; nt++)
#pragma unroll
            for (int i = 0; i < 4; i++) acc[mt][nt][i] = 0.0f;

    auto load_tiles = [&](int buf, int kt) {
        const int k0u = kt * 16;
#pragma unroll
        for (int it = 0; it < 4; it++) {
            int c = it * 256 + tid;
            int tile = c >> 9;
            int r = (c >> 2) & 127;
            int ch = c & 3;
            uint32_t dst = sb + (uint32_t)(buf * STAGE_B + tile * TILE_B) + swz((uint32_t)r, (uint32_t)ch);
            const uint32_t* src;
            bool p = true;
            if (tile == 0) {
                int gr = row0 + r;
                p = gr < Mm;
                int gra = p ? gr : 0;
                src = A2 + (size_t)gra * Ku + k0u + ch * 4;
            } else {
                int gn = col0 + r;
                src = B2 + (size_t)gn * Ku + k0u + ch * 4;
            }
            cp16(dst, src, p);
        }
        asm volatile("cp.async.commit_group;" ::: "memory");
    };

    const int nkt = Kk / 32;
    load_tiles(0, 0);

    const uint32_t aR = (uint32_t)(m0 + (lid & 15));
    const uint32_t aC = (uint32_t)(lid >> 4);
    const uint32_t bR = (uint32_t)(n0 + (lid & 7));
    const uint32_t bC = (uint32_t)((lid >> 3) & 1);

    for (int kt = 0; kt < nkt; kt++) {
        int buf = kt & 1;
        if (kt + 1 < nkt) {
            load_tiles(buf ^ 1, kt + 1);
            asm volatile("cp.async.wait_group 1;" ::: "memory");
        } else {
            asm volatile("cp.async.wait_group 0;" ::: "memory");
        }
        __syncthreads();

        const uint32_t base = sb + (uint32_t)(buf * STAGE_B);

#pragma unroll
        for (int ks = 0; ks < 2; ks++) {
            uint32_t ah[4][4];
            uint32_t bq[4][2];
#pragma unroll
            for (int mt = 0; mt < 4; mt++)
                ldsm_x4(ah[mt], base + swz(aR + mt * 16, aC + ks * 2));
#pragma unroll
            for (int nt = 0; nt < 4; nt++)
                ldsm_x2(bq[nt], base + TILE_B + swz(bR + nt * 8, bC + ks * 2));

#pragma unroll
            for (int mt = 0; mt < 4; mt++)
#pragma unroll
                for (int nt = 0; nt < 4; nt++)
                    mma_f16(acc[mt][nt], ah[mt], bq[nt]);
        }
        __syncthreads();
    }

    // ---- epilogue (packed half2 out) ----
#pragma unroll
    for (int mt = 0; mt < 4; mt++) {
        int r0 = row0 + m0 + mt * 16 + g;
        int r1 = r0 + 8;
        if (EPI_TANH) {
#pragma unroll
            for (int nt = 0; nt < 4; nt++) {
                int cn = col0 + n0 + nt * 8 + t * 2;
                float bx = bias[cn], by = bias[cn + 1];
                if (r0 < Mm)
                    Ch[((size_t)r0 * Nn + cn) >> 1] =
                        pack2h(tanhf(acc[mt][nt][0] + bx), tanhf(acc[mt][nt][1] + by));
                if (r1 < Mm)
                    Ch[((size_t)r1 * Nn + cn) >> 1] =
                        pack2h(tanhf(acc[mt][nt][2] + bx), tanhf(acc[mt][nt][3] + by));
            }
        } else {
            float s0 = (r0 < Mm) ? dinv[r0] : 0.0f;
            float s1 = (r1 < Mm) ? dinv[r1] : 0.0f;
#pragma unroll
            for (int nt = 0; nt < 4; nt++) {
                int cn = col0 + n0 + nt * 8 + t * 2;
                if (r0 < Mm)
                    Ch[((size_t)r0 * Nn + cn) >> 1] = pack2h(acc[mt][nt][0] * s0, acc[mt][nt][1] * s0);
                if (r1 < Mm)
                    Ch[((size_t)r1 * Nn + cn) >> 1] = pack2h(acc[mt][nt][2] * s1, acc[mt][nt][3] * s1);
            }
        }
    }
}

// ---------------- layer-2 aggregation (512-wide, uint4 16B gathers, tanh, fp16 out) ----------------
__global__ void agg_h512_kernel(const __half* __restrict__ G,
                                const float* __restrict__ bias,
                                const float* __restrict__ dinv,
                                const int* __restrict__ rowptr,
                                const int* __restrict__ colsrc,
                                uint4* __restrict__ outH)
{
    const int F8 = HID_DIM / 8;   // 64 threads, 8 halves each
    int i = blockIdx.x;
    int t = threadIdx.x;
    const uint4* G8 = (const uint4*)G;

    float acc[8];
#pragma unroll
    for (int k = 0; k < 8; k++) acc[k] = 0.0f;

    auto unpack_add = [&](uint4 v) {
        __half2 p0 = *reinterpret_cast<__half2*>(&v.x);
        __half2 p1 = *reinterpret_cast<__half2*>(&v.y);
        __half2 p2 = *reinterpret_cast<__half2*>(&v.z);
        __half2 p3 = *reinterpret_cast<__half2*>(&v.w);
        float2 f0 = __half22float2(p0);
        float2 f1 = __half22float2(p1);
        float2 f2 = __half22float2(p2);
        float2 f3 = __half22float2(p3);
        acc[0] += f0.x; acc[1] += f0.y; acc[2] += f1.x; acc[3] += f1.y;
        acc[4] += f2.x; acc[5] += f2.y; acc[6] += f3.x; acc[7] += f3.y;
    };

    unpack_add(__ldg(&G8[(size_t)i * F8 + t]));

    int e   = rowptr[i];
    int end = rowptr[i + 1];
    for (; e + 4 <= end; e += 4) {
        int s0 = __ldg(&colsrc[e + 0]);
        int s1 = __ldg(&colsrc[e + 1]);
        int s2 = __ldg(&colsrc[e + 2]);
        int s3 = __ldg(&colsrc[e + 3]);
        uint4 v0 = __ldg(&G8[(size_t)s0 * F8 + t]);
        uint4 v1 = __ldg(&G8[(size_t)s1 * F8 + t]);
        uint4 v2 = __ldg(&G8[(size_t)s2 * F8 + t]);
        uint4 v3 = __ldg(&G8[(size_t)s3 * F8 + t]);
        unpack_add(v0); unpack_add(v1); unpack_add(v2); unpack_add(v3);
    }
    for (; e < end; ++e) {
        int s = __ldg(&colsrc[e]);
        unpack_add(__ldg(&G8[(size_t)s * F8 + t]));
    }

    float di = dinv[i];
    const float* b8 = bias + t * 8;
    float r[8];
#pragma unroll
    for (int k = 0; k < 8; k++)
        r[k] = tanhf(fmaf(acc[k], di, __ldg(&b8[k])));

    outH[(size_t)i * F8 + t] = make_uint4(pack2h(r[0], r[1]), pack2h(r[2], r[3]),
                                          pack2h(r[4], r[5]), pack2h(r[6], r[7]));
}

// ---------------- layer-3 aggregation (256-wide, bias, fp32 out) ----------------
__global__ void agg_out_kernel(const __half* __restrict__ G,
                               const float* __restrict__ bias,
                               const float* __restrict__ dinv,
                               const int* __restrict__ rowptr,
                               const int* __restrict__ colsrc,
                               float* __restrict__ outF)
{
    const int F4 = OUT_DIM / 4;   // 64
    int i = blockIdx.x;
    int t = threadIdx.x;
    const uint2* G4 = (const uint2*)G;

    auto unpack_add = [](float4& a, uint2 v) {
        __half2 p0 = *reinterpret_cast<__half2*>(&v.x);
        __half2 p1 = *reinterpret_cast<__half2*>(&v.y);
        float2 f0 = __half22float2(p0);
        float2 f1 = __half22float2(p1);
        a.x += f0.x; a.y += f0.y; a.z += f1.x; a.w += f1.y;
    };

    float4 acc = make_float4(0.f, 0.f, 0.f, 0.f);
    unpack_add(acc, __ldg(&G4[(size_t)i * F4 + t]));

    int e   = rowptr[i];
    int end = rowptr[i + 1];
    for (; e + 4 <= end; e += 4) {
        int s0 = __ldg(&colsrc[e + 0]);
        int s1 = __ldg(&colsrc[e + 1]);
        int s2 = __ldg(&colsrc[e + 2]);
        int s3 = __ldg(&colsrc[e + 3]);
        uint2 v0 = __ldg(&G4[(size_t)s0 * F4 + t]);
        uint2 v1 = __ldg(&G4[(size_t)s1 * F4 + t]);
        uint2 v2 = __ldg(&G4[(size_t)s2 * F4 + t]);
        uint2 v3 = __ldg(&G4[(size_t)s3 * F4 + t]);
        unpack_add(acc, v0); unpack_add(acc, v1);
        unpack_add(acc, v2); unpack_add(acc, v3);
    }
    for (; e < end; ++e) {
        int s = __ldg(&colsrc[e]);
        unpack_add(acc, __ldg(&G4[(size_t)s * F4 + t]));
    }

    float di = dinv[i];
    float4 bb = ((const float4*)bias)[t];
    float4 r;
    r.x = fmaf(acc.x, di, bb.x);
    r.y = fmaf(acc.y, di, bb.y);
    r.z = fmaf(acc.z, di, bb.z);
    r.w = fmaf(acc.w, di, bb.w);
    ((float4*)outF)[(size_t)i * F4 + t] = r;
}

// ---------------- launch ----------------
extern "C" void kernel_launch(void* const* d_in, const int* in_sizes, int n_in,
                              void* d_out, int out_size) {
    const float* x  = (const float*)d_in[0];
    const float* W1 = (const float*)d_in[1];
    const float* b1 = (const float*)d_in[2];
    const float* W2 = (const float*)d_in[3];
    const float* b2 = (const float*)d_in[4];
    const float* W3 = (const float*)d_in[5];
    const float* b3 = (const float*)d_in[6];
    const int*   ei = (const int*)d_in[7];    // int32 edge_index [2, E]
    float* out = (float*)d_out;

    const int N = N_NODES;
    const int E = in_sizes[7] / 2;

    float *dinv;
    int *cnt, *rowptr, *cursor, *colsrc;
    __half *bufH, *hiA, *hiB, *w1t, *w2t, *w3t;
    cudaGetSymbolAddress((void**)&bufH,   g_bufH);
    cudaGetSymbolAddress((void**)&dinv,   g_dinv);
    cudaGetSymbolAddress((void**)&cnt,    g_cnt);
    cudaGetSymbolAddress((void**)&rowptr, g_rowptr);
    cudaGetSymbolAddress((void**)&cursor, g_cursor);
    cudaGetSymbolAddress((void**)&colsrc, g_colsrc);
    cudaGetSymbolAddress((void**)&hiA,    g_hiA);
    cudaGetSymbolAddress((void**)&hiB,    g_hiB);
    cudaGetSymbolAddress((void**)&w1t,    g_W1t);
    cudaGetSymbolAddress((void**)&w2t,    g_W2t);
    cudaGetSymbolAddress((void**)&w3t,    g_W3t);

    static bool attr_set = false;
    if (!attr_set) {
        cudaFuncSetAttribute(gemm_mma_kernel<0>, cudaFuncAttributeMaxDynamicSharedMemorySize, GEMM_SMEM);
        cudaFuncSetAttribute(gemm_mma_kernel<1>, cudaFuncAttributeMaxDynamicSharedMemorySize, GEMM_SMEM);
        attr_set = true;
    }

    // --- fused one-shot prep (W fp16 transpose, cnt zero) ---
    fused_prep_kernel<<<(WTOT + N + 255) / 256, 256>>>(W1, W2, W3, w1t, w2t, w3t, cnt);
    // --- CSR by dst ---
    count_edges_kernel<<<(E / 2 + 255) / 256, 256>>>(ei, cnt, E);
    scan_kernel<<<1, 1024>>>(cnt, rowptr, cursor, dinv, N);
    fill_csr_kernel<<<(E / 2 + 255) / 256, 256>>>(ei, cursor, colsrc, E);

    const int MT = (N + 127) / 128;

    // --- layer 1: aggregate fp32 x (256-wide) -> fp16, then GEMM with tanh epilogue ---
    agg_x_kernel<<<N, IN_DIM / 4>>>(x, dinv, rowptr, colsrc, (uint2*)hiA);
    {
        dim3 grid(HID_DIM / 128, MT);
        gemm_mma_kernel<1><<<grid, 256, GEMM_SMEM>>>((uint32_t*)hiA, (uint32_t*)w1t,
                                                     nullptr, b1, (uint32_t*)hiB,
                                                     N, HID_DIM, IN_DIM);
    }
    // --- layer 2: GEMM (dinv epi, fp16 out) -> agg (uint4 gathers, tanh, fp16 out) ---
    {
        dim3 grid(HID_DIM / 128, MT);
        gemm_mma_kernel<0><<<grid, 256, GEMM_SMEM>>>((uint32_t*)hiB, (uint32_t*)w2t,
                                                     dinv, nullptr, (uint32_t*)bufH,
                                                     N, HID_DIM, HID_DIM);
        agg_h512_kernel<<<N, HID_DIM / 8>>>(bufH, b2, dinv, rowptr, colsrc, (uint4*)hiA);
    }
    // --- layer 3: GEMM (dinv epi, fp16 out) -> agg (bias, fp32 out) ---
    {
        dim3 grid(OUT_DIM / 128, MT);
        gemm_mma_kernel<0><<<grid, 256, GEMM_SMEM>>>((uint32_t*)hiA, (uint32_t*)w3t,
                                                     dinv, nullptr, (uint32_t*)bufH,
                                                     N, OUT_DIM, HID_DIM);
        agg_out_kernel<<<N, OUT_DIM / 4>>>(bufH, b3, dinv, rowptr, colsrc, out);
    }
}